// round 1
// baseline (speedup 1.0000x reference)
#include <cuda_runtime.h>
#include <float.h>

#define NUM_SEQS 64
#define NUM_HEADS 32
#define NUM_KV_HEADS 8
#define HEAD_SIZE 128
#define BLOCK_SIZE 16
#define MAX_BLOCKS_PER_SEQ 64
#define Q_PER_KV 4
#define ATTN_SCALE 0.08838834764831845f

#define NWARPS 8
#define QSTRIDE 136   // padded per-head stride (floats); halves at +0 / +68 -> no smem bank conflict

__global__ __launch_bounds__(256, 2)
void paged_attn_kernel(const float* __restrict__ query,
                       const float* __restrict__ key_cache,
                       const float* __restrict__ value_cache,
                       const int*   __restrict__ block_tables,
                       const int*   __restrict__ context_lens,
                       float*       __restrict__ out)
{
    const int kvh  = blockIdx.x;   // 0..7
    const int seq  = blockIdx.y;   // 0..63
    const int tid  = threadIdx.x;
    const int warp = tid >> 5;
    const int lane = tid & 31;

    __shared__ float q_s[Q_PER_KV * QSTRIDE];
    __shared__ float w_m[NWARPS][Q_PER_KV];
    __shared__ float w_l[NWARPS][Q_PER_KV];
    __shared__ float w_acc[NWARPS][Q_PER_KV][HEAD_SIZE];

    // Stage q (pre-scaled). Layout: q_s[h*136 + (d>>6)*68 + (d&63)]
    for (int i = tid; i < Q_PER_KV * HEAD_SIZE; i += 256) {
        int h = i >> 7;
        int d = i & 127;
        q_s[h * QSTRIDE + (d >> 6) * 68 + (d & 63)] =
            query[(size_t)(seq * NUM_HEADS + kvh * Q_PER_KV + h) * HEAD_SIZE + d] * ATTN_SCALE;
    }
    __syncthreads();

    const int ctx     = context_lens[seq];
    const int nblocks = (ctx + BLOCK_SIZE - 1) / BLOCK_SIZE;
    const int* btab   = block_tables + seq * MAX_BLOCKS_PER_SEQ;

    const int t_lane = lane >> 1;  // token this lane pair scores (0..15)
    const int halfk  = lane & 1;   // which 64-dim half this lane sums

    float m[Q_PER_KV]   = { -1e30f, -1e30f, -1e30f, -1e30f };
    float lsum[Q_PER_KV] = { 0.f, 0.f, 0.f, 0.f };
    float acc[Q_PER_KV][4] = { {0,0,0,0},{0,0,0,0},{0,0,0,0},{0,0,0,0} };

    for (int blk = warp; blk < nblocks; blk += NWARPS) {
        const int pb = btab[blk];
        const size_t base = ((size_t)pb * NUM_KV_HEADS + kvh) * 2048;  // 16*16*8 = 128*16 floats

        // ---- K: layout [hs/8=16][bs=16][8]; element (dh,t,dl) at dh*128 + t*8 + dl
        // lane loads dims d = halfk*64 + i*8 + dl for its token; 16x LDG.128 in flight
        const float4* kb = (const float4*)(key_cache + base);
        float4 kr[16];
        #pragma unroll
        for (int i = 0; i < 8; i++) {
            int f4i = (halfk * 8 + i) * 32 + t_lane * 2;
            kr[2 * i]     = kb[f4i];
            kr[2 * i + 1] = kb[f4i + 1];
        }

        // ---- scores (4 heads), q from smem (broadcast, 1-phase via padding)
        float s[Q_PER_KV] = { 0.f, 0.f, 0.f, 0.f };
        #pragma unroll
        for (int i = 0; i < 8; i++) {
            const float4 ka = kr[2 * i];
            const float4 kc = kr[2 * i + 1];
            #pragma unroll
            for (int h = 0; h < Q_PER_KV; h++) {
                const float4* qp = (const float4*)(q_s + h * QSTRIDE + halfk * 68 + i * 8);
                const float4 qa = qp[0];
                const float4 qb = qp[1];
                s[h] += ka.x * qa.x + ka.y * qa.y + ka.z * qa.z + ka.w * qa.w
                      + kc.x * qb.x + kc.y * qb.y + kc.z * qb.z + kc.w * qb.w;
            }
        }
        // combine the two half-dim partials within the lane pair
        #pragma unroll
        for (int h = 0; h < Q_PER_KV; h++)
            s[h] += __shfl_xor_sync(0xffffffffu, s[h], 1);

        const bool valid = (blk * BLOCK_SIZE + t_lane) < ctx;
        #pragma unroll
        for (int h = 0; h < Q_PER_KV; h++)
            s[h] = valid ? s[h] : -1e30f;

        // ---- online softmax update (per warp, per head)
        float p[Q_PER_KV];
        #pragma unroll
        for (int h = 0; h < Q_PER_KV; h++) {
            float bm = s[h];
            #pragma unroll
            for (int off = 2; off < 32; off <<= 1)
                bm = fmaxf(bm, __shfl_xor_sync(0xffffffffu, bm, off));
            const float mn   = fmaxf(m[h], bm);
            const float corr = __expf(m[h] - mn);
            p[h] = __expf(s[h] - mn);
            float ps = p[h];
            #pragma unroll
            for (int off = 2; off < 32; off <<= 1)
                ps += __shfl_xor_sync(0xffffffffu, ps, off);
            lsum[h] = lsum[h] * corr + ps;
            m[h] = mn;
            #pragma unroll
            for (int r = 0; r < 4; r++) acc[h][r] *= corr;
        }

        // ---- V: layout [hs=128][bs=16]; lane owns dims lane*4 .. lane*4+3 (rows are contiguous 64B)
        const float* vb = value_cache + base + (size_t)(lane * 4) * BLOCK_SIZE;
        #pragma unroll
        for (int tc = 0; tc < 4; tc++) {
            const float4 v0 = *(const float4*)(vb + 0 * 16 + tc * 4);
            const float4 v1 = *(const float4*)(vb + 1 * 16 + tc * 4);
            const float4 v2 = *(const float4*)(vb + 2 * 16 + tc * 4);
            const float4 v3 = *(const float4*)(vb + 3 * 16 + tc * 4);
            #pragma unroll
            for (int h = 0; h < Q_PER_KV; h++) {
                const float p0 = __shfl_sync(0xffffffffu, p[h], (4 * tc + 0) * 2);
                const float p1 = __shfl_sync(0xffffffffu, p[h], (4 * tc + 1) * 2);
                const float p2 = __shfl_sync(0xffffffffu, p[h], (4 * tc + 2) * 2);
                const float p3 = __shfl_sync(0xffffffffu, p[h], (4 * tc + 3) * 2);
                acc[h][0] += p0 * v0.x + p1 * v0.y + p2 * v0.z + p3 * v0.w;
                acc[h][1] += p0 * v1.x + p1 * v1.y + p2 * v1.z + p3 * v1.w;
                acc[h][2] += p0 * v2.x + p1 * v2.y + p2 * v2.z + p3 * v2.w;
                acc[h][3] += p0 * v3.x + p1 * v3.y + p2 * v3.z + p3 * v3.w;
            }
        }
    }

    // ---- publish per-warp partials
    if (lane == 0) {
        #pragma unroll
        for (int h = 0; h < Q_PER_KV; h++) { w_m[warp][h] = m[h]; w_l[warp][h] = lsum[h]; }
    }
    #pragma unroll
    for (int h = 0; h < Q_PER_KV; h++)
        *(float4*)&w_acc[warp][h][lane * 4] = make_float4(acc[h][0], acc[h][1], acc[h][2], acc[h][3]);
    __syncthreads();

    // ---- merge 8 warps (flash-decoding combine) and write out
    for (int o = tid; o < Q_PER_KV * HEAD_SIZE; o += 256) {
        const int h = o >> 7;
        const int d = o & 127;
        float mg = -1e30f;
        #pragma unroll
        for (int w = 0; w < NWARPS; w++) mg = fmaxf(mg, w_m[w][h]);
        float num = 0.f, den = 0.f;
        #pragma unroll
        for (int w = 0; w < NWARPS; w++) {
            const float f = __expf(w_m[w][h] - mg);
            num += w_acc[w][h][d] * f;
            den += w_l[w][h] * f;
        }
        out[(size_t)(seq * NUM_HEADS + kvh * Q_PER_KV + h) * HEAD_SIZE + d] = num / den;
    }
}

extern "C" void kernel_launch(void* const* d_in, const int* in_sizes, int n_in,
                              void* d_out, int out_size)
{
    const float* query       = (const float*)d_in[0];
    const float* key_cache   = (const float*)d_in[1];
    const float* value_cache = (const float*)d_in[2];
    const int*   block_tables  = (const int*)d_in[3];
    const int*   context_lens  = (const int*)d_in[4];
    float* out = (float*)d_out;

    dim3 grid(NUM_KV_HEADS, NUM_SEQS);
    paged_attn_kernel<<<grid, 256>>>(query, key_cache, value_cache,
                                     block_tables, context_lens, out);
}

// round 2
// speedup vs baseline: 1.8950x; 1.8950x over previous
#include <cuda_runtime.h>
#include <float.h>

#define NUM_SEQS 64
#define NUM_HEADS 32
#define NUM_KV_HEADS 8
#define HEAD_SIZE 128
#define BLOCK_SIZE 16
#define MAX_BLOCKS_PER_SEQ 64
#define Q_PER_KV 4
#define ATTN_SCALE 0.08838834764831845f

#define NWARPS 8
#define SPLITS 8
#define BLOCKS_PER_SPLIT 8           // = NWARPS: one block per warp
#define QSTRIDE 136                  // padded per-head stride; halves at +0/+68

// split-K partial scratch (written every run before read; no alloc APIs)
__device__ float g_acc[NUM_SEQS][NUM_KV_HEADS][SPLITS][Q_PER_KV][HEAD_SIZE];
__device__ float g_ml [NUM_SEQS][NUM_KV_HEADS][SPLITS][Q_PER_KV][2];

__global__ __launch_bounds__(256, 2)
void paged_attn_partial(const float* __restrict__ query,
                        const float* __restrict__ key_cache,
                        const float* __restrict__ value_cache,
                        const int*   __restrict__ block_tables,
                        const int*   __restrict__ context_lens)
{
    const int kvh   = blockIdx.x;   // 0..7
    const int seq   = blockIdx.y;   // 0..63
    const int split = blockIdx.z;   // 0..7
    const int tid   = threadIdx.x;
    const int warp  = tid >> 5;
    const int lane  = tid & 31;

    const int ctx     = context_lens[seq];
    const int nblocks = (ctx + BLOCK_SIZE - 1) / BLOCK_SIZE;
    if (split * BLOCKS_PER_SPLIT >= nblocks) return;   // uniform across CTA

    __shared__ float q_s[Q_PER_KV * QSTRIDE];
    __shared__ float w_m[NWARPS][Q_PER_KV];
    __shared__ float w_l[NWARPS][Q_PER_KV];
    __shared__ float w_acc[NWARPS][Q_PER_KV][HEAD_SIZE];

    // Stage q (pre-scaled). q_s[h*136 + (d>>6)*68 + (d&63)]
    for (int i = tid; i < Q_PER_KV * HEAD_SIZE; i += 256) {
        int h = i >> 7;
        int d = i & 127;
        q_s[h * QSTRIDE + (d >> 6) * 68 + (d & 63)] =
            query[(size_t)(seq * NUM_HEADS + kvh * Q_PER_KV + h) * HEAD_SIZE + d] * ATTN_SCALE;
    }
    __syncthreads();

    const int blk = split * BLOCKS_PER_SPLIT + warp;   // this warp's single KV block

    const int t_lane = lane >> 1;   // token (0..15) this lane pair scores
    const int halfk  = lane & 1;    // which 64-dim half this lane sums

    float m[Q_PER_KV]    = { -1e30f, -1e30f, -1e30f, -1e30f };
    float lsum[Q_PER_KV] = { 0.f, 0.f, 0.f, 0.f };
    float acc[Q_PER_KV][4] = { {0,0,0,0},{0,0,0,0},{0,0,0,0},{0,0,0,0} };

    if (blk < nblocks) {
        const int pb = block_tables[seq * MAX_BLOCKS_PER_SEQ + blk];
        const size_t base = ((size_t)pb * NUM_KV_HEADS + kvh) * 2048;

        // ---- K: [hs/8=16][bs=16][8]; lane loads dims halfk*64 + i*8 .. +7 of its token
        const float4* kb = (const float4*)(key_cache + base);
        float4 kr[16];
        #pragma unroll
        for (int i = 0; i < 8; i++) {
            int f4i = (halfk * 8 + i) * 32 + t_lane * 2;
            kr[2 * i]     = kb[f4i];
            kr[2 * i + 1] = kb[f4i + 1];
        }

        // ---- scores for 4 heads (q broadcast from padded smem)
        float s[Q_PER_KV] = { 0.f, 0.f, 0.f, 0.f };
        #pragma unroll
        for (int i = 0; i < 8; i++) {
            const float4 ka = kr[2 * i];
            const float4 kc = kr[2 * i + 1];
            #pragma unroll
            for (int h = 0; h < Q_PER_KV; h++) {
                const float4* qp = (const float4*)(q_s + h * QSTRIDE + halfk * 68 + i * 8);
                const float4 qa = qp[0];
                const float4 qb = qp[1];
                s[h] += ka.x * qa.x + ka.y * qa.y + ka.z * qa.z + ka.w * qa.w
                      + kc.x * qb.x + kc.y * qb.y + kc.z * qb.z + kc.w * qb.w;
            }
        }
        #pragma unroll
        for (int h = 0; h < Q_PER_KV; h++)
            s[h] += __shfl_xor_sync(0xffffffffu, s[h], 1);

        const bool valid = (blk * BLOCK_SIZE + t_lane) < ctx;
        #pragma unroll
        for (int h = 0; h < Q_PER_KV; h++)
            s[h] = valid ? s[h] : -1e30f;

        // ---- single softmax pass (no online rescale: one block per warp)
        float p[Q_PER_KV];
        #pragma unroll
        for (int h = 0; h < Q_PER_KV; h++) {
            float bm = s[h];
            #pragma unroll
            for (int off = 2; off < 32; off <<= 1)
                bm = fmaxf(bm, __shfl_xor_sync(0xffffffffu, bm, off));
            p[h] = __expf(s[h] - bm);
            float ps = p[h];
            #pragma unroll
            for (int off = 2; off < 32; off <<= 1)
                ps += __shfl_xor_sync(0xffffffffu, ps, off);
            m[h]    = bm;
            lsum[h] = ps;
        }

        // ---- V: [hs=128][bs=16]; lane owns dims lane*4..lane*4+3
        const float* vb = value_cache + base + (size_t)(lane * 4) * BLOCK_SIZE;
        #pragma unroll
        for (int tc = 0; tc < 4; tc++) {
            const float4 v0 = *(const float4*)(vb + 0 * 16 + tc * 4);
            const float4 v1 = *(const float4*)(vb + 1 * 16 + tc * 4);
            const float4 v2 = *(const float4*)(vb + 2 * 16 + tc * 4);
            const float4 v3 = *(const float4*)(vb + 3 * 16 + tc * 4);
            #pragma unroll
            for (int h = 0; h < Q_PER_KV; h++) {
                const float p0 = __shfl_sync(0xffffffffu, p[h], (4 * tc + 0) * 2);
                const float p1 = __shfl_sync(0xffffffffu, p[h], (4 * tc + 1) * 2);
                const float p2 = __shfl_sync(0xffffffffu, p[h], (4 * tc + 2) * 2);
                const float p3 = __shfl_sync(0xffffffffu, p[h], (4 * tc + 3) * 2);
                acc[h][0] += p0 * v0.x + p1 * v0.y + p2 * v0.z + p3 * v0.w;
                acc[h][1] += p0 * v1.x + p1 * v1.y + p2 * v1.z + p3 * v1.w;
                acc[h][2] += p0 * v2.x + p1 * v2.y + p2 * v2.z + p3 * v2.w;
                acc[h][3] += p0 * v3.x + p1 * v3.y + p2 * v3.z + p3 * v3.w;
            }
        }
    }

    // ---- publish per-warp partials
    if (lane == 0) {
        #pragma unroll
        for (int h = 0; h < Q_PER_KV; h++) { w_m[warp][h] = m[h]; w_l[warp][h] = lsum[h]; }
    }
    #pragma unroll
    for (int h = 0; h < Q_PER_KV; h++)
        *(float4*)&w_acc[warp][h][lane * 4] = make_float4(acc[h][0], acc[h][1], acc[h][2], acc[h][3]);
    __syncthreads();

    // ---- merge 8 warps, write split partial to scratch
    if (tid < Q_PER_KV) {
        const int h = tid;
        float mg = -1e30f;
        #pragma unroll
        for (int w = 0; w < NWARPS; w++) mg = fmaxf(mg, w_m[w][h]);
        float den = 0.f;
        #pragma unroll
        for (int w = 0; w < NWARPS; w++) den += w_l[w][h] * __expf(w_m[w][h] - mg);
        g_ml[seq][kvh][split][h][0] = mg;
        g_ml[seq][kvh][split][h][1] = den;
    }
    for (int o = tid; o < Q_PER_KV * HEAD_SIZE; o += 256) {
        const int h = o >> 7;
        const int d = o & 127;
        float mg = -1e30f;
        #pragma unroll
        for (int w = 0; w < NWARPS; w++) mg = fmaxf(mg, w_m[w][h]);
        float num = 0.f;
        #pragma unroll
        for (int w = 0; w < NWARPS; w++) num += w_acc[w][h][d] * __expf(w_m[w][h] - mg);
        g_acc[seq][kvh][split][h][d] = num;
    }
}

__global__ __launch_bounds__(128)
void paged_attn_merge(const int* __restrict__ context_lens,
                      float* __restrict__ out)
{
    const int seq  = blockIdx.x;    // 0..63
    const int head = blockIdx.y;    // 0..31
    const int kvh  = head >> 2;
    const int h    = head & 3;
    const int d    = threadIdx.x;   // 0..127

    const int ctx     = context_lens[seq];
    const int nblocks = (ctx + BLOCK_SIZE - 1) / BLOCK_SIZE;
    const int nsplits = (nblocks + BLOCKS_PER_SPLIT - 1) / BLOCKS_PER_SPLIT;

    float gm = -1e30f;
    for (int s = 0; s < nsplits; s++)
        gm = fmaxf(gm, g_ml[seq][kvh][s][h][0]);

    float num = 0.f, den = 0.f;
    for (int s = 0; s < nsplits; s++) {
        const float f = __expf(g_ml[seq][kvh][s][h][0] - gm);
        num += g_acc[seq][kvh][s][h][d] * f;
        den += g_ml[seq][kvh][s][h][1] * f;
    }
    out[(size_t)(seq * NUM_HEADS + head) * HEAD_SIZE + d] = num / den;
}

extern "C" void kernel_launch(void* const* d_in, const int* in_sizes, int n_in,
                              void* d_out, int out_size)
{
    const float* query       = (const float*)d_in[0];
    const float* key_cache   = (const float*)d_in[1];
    const float* value_cache = (const float*)d_in[2];
    const int*   block_tables  = (const int*)d_in[3];
    const int*   context_lens  = (const int*)d_in[4];
    float* out = (float*)d_out;

    dim3 grid1(NUM_KV_HEADS, NUM_SEQS, SPLITS);
    paged_attn_partial<<<grid1, 256>>>(query, key_cache, value_cache,
                                       block_tables, context_lens);
    dim3 grid2(NUM_SEQS, NUM_HEADS);
    paged_attn_merge<<<grid2, 128>>>(context_lens, out);
}

// round 3
// speedup vs baseline: 2.4025x; 1.2678x over previous
#include <cuda_runtime.h>
#include <float.h>

#define NUM_SEQS 64
#define NUM_HEADS 32
#define NUM_KV_HEADS 8
#define HEAD_SIZE 128
#define BLOCK_SIZE 16
#define MAX_BLOCKS_PER_SEQ 64
#define Q_PER_KV 4
#define ATTN_SCALE 0.08838834764831845f

#define NWARPS 8
#define SPLITS 8
#define BLOCKS_PER_SPLIT 8
#define QSTRIDE 136

__device__ float g_acc[NUM_SEQS][NUM_KV_HEADS][SPLITS][Q_PER_KV][HEAD_SIZE];
__device__ float g_ml [NUM_SEQS][NUM_KV_HEADS][SPLITS][Q_PER_KV][2];

__global__ __launch_bounds__(256, 2)
void paged_attn_partial(const float* __restrict__ query,
                        const float* __restrict__ key_cache,
                        const float* __restrict__ value_cache,
                        const int*   __restrict__ block_tables,
                        const int*   __restrict__ context_lens)
{
    const int kvh   = blockIdx.x;
    const int seq   = blockIdx.y;
    const int split = blockIdx.z;
    const int tid   = threadIdx.x;
    const int warp  = tid >> 5;
    const int lane  = tid & 31;

    const int ctx     = context_lens[seq];
    const int nblocks = (ctx + BLOCK_SIZE - 1) / BLOCK_SIZE;
    if (split * BLOCKS_PER_SPLIT >= nblocks) return;

    __shared__ float q_s[Q_PER_KV * QSTRIDE];
    __shared__ float w_m[NWARPS][Q_PER_KV];
    __shared__ float w_l[NWARPS][Q_PER_KV];
    __shared__ float w_acc[NWARPS][Q_PER_KV][HEAD_SIZE];

    for (int i = tid; i < Q_PER_KV * HEAD_SIZE; i += 256) {
        int h = i >> 7;
        int d = i & 127;
        q_s[h * QSTRIDE + (d >> 6) * 68 + (d & 63)] =
            query[(size_t)(seq * NUM_HEADS + kvh * Q_PER_KV + h) * HEAD_SIZE + d] * ATTN_SCALE;
    }
    // zero w_acc so inactive warps (blk >= nblocks) contribute nothing
    for (int i = tid; i < NWARPS * Q_PER_KV * HEAD_SIZE; i += 256)
        ((float*)w_acc)[i] = 0.f;
    __syncthreads();

    const int blk = split * BLOCKS_PER_SPLIT + warp;

    const int t_lane = lane >> 1;
    const int halfk  = lane & 1;

    float m[Q_PER_KV]    = { -1e30f, -1e30f, -1e30f, -1e30f };
    float lsum[Q_PER_KV] = { 0.f, 0.f, 0.f, 0.f };

    if (blk < nblocks) {
        const int pb = block_tables[seq * MAX_BLOCKS_PER_SEQ + blk];
        const size_t base = ((size_t)pb * NUM_KV_HEADS + kvh) * 2048;

        // ---- prefetch V tile (8KB) to L2 while K phase runs
        {
            const char* vpre = (const char*)(value_cache + base);
            asm volatile("prefetch.global.L2 [%0];" :: "l"(vpre + lane * 128));
            asm volatile("prefetch.global.L2 [%0];" :: "l"(vpre + 4096 + lane * 128));
        }

        // ---- K: [hs/8=16][bs=16][8]; lane loads dims halfk*64 + i*8..+7 of its token
        const float4* kb = (const float4*)(key_cache + base);
        float4 kr[16];
        #pragma unroll
        for (int i = 0; i < 8; i++) {
            int f4i = (halfk * 8 + i) * 32 + t_lane * 2;
            kr[2 * i]     = kb[f4i];
            kr[2 * i + 1] = kb[f4i + 1];
        }

        float s[Q_PER_KV] = { 0.f, 0.f, 0.f, 0.f };
        #pragma unroll
        for (int i = 0; i < 8; i++) {
            const float4 ka = kr[2 * i];
            const float4 kc = kr[2 * i + 1];
            #pragma unroll
            for (int h = 0; h < Q_PER_KV; h++) {
                const float4* qp = (const float4*)(q_s + h * QSTRIDE + halfk * 68 + i * 8);
                const float4 qa = qp[0];
                const float4 qb = qp[1];
                s[h] += ka.x * qa.x + ka.y * qa.y + ka.z * qa.z + ka.w * qa.w
                      + kc.x * qb.x + kc.y * qb.y + kc.z * qb.z + kc.w * qb.w;
            }
        }
        #pragma unroll
        for (int h = 0; h < Q_PER_KV; h++)
            s[h] += __shfl_xor_sync(0xffffffffu, s[h], 1);

        const bool valid = (blk * BLOCK_SIZE + t_lane) < ctx;
        #pragma unroll
        for (int h = 0; h < Q_PER_KV; h++)
            s[h] = valid ? s[h] : -1e30f;

        // ---- softmax over the 16 tokens (p for token t lives on lanes 2t, 2t+1)
        float p[Q_PER_KV];
        #pragma unroll
        for (int h = 0; h < Q_PER_KV; h++) {
            float bm = s[h];
            #pragma unroll
            for (int off = 2; off < 32; off <<= 1)
                bm = fmaxf(bm, __shfl_xor_sync(0xffffffffu, bm, off));
            p[h] = __expf(s[h] - bm);
            float ps = p[h];
            #pragma unroll
            for (int off = 2; off < 32; off <<= 1)
                ps += __shfl_xor_sync(0xffffffffu, ps, off);
            m[h]    = bm;
            lsum[h] = ps;
        }
        if (lane == 0) {
            #pragma unroll
            for (int h = 0; h < Q_PER_KV; h++) { w_m[warp][h] = m[h]; w_l[warp][h] = lsum[h]; }
        }

        // ---- V, coalesced: lane reads float4 at k*128 + lane*4 floats
        //      -> v[dim = k*8 + lane/4][tokens (lane&3)*4 .. +3]
        // fetch this lane's 4 token-probs per head once
        float ptok[Q_PER_KV][4];
        const int tok0 = (lane & 3) * 4;
        #pragma unroll
        for (int h = 0; h < Q_PER_KV; h++)
            #pragma unroll
            for (int j = 0; j < 4; j++)
                ptok[h][j] = __shfl_sync(0xffffffffu, p[h], (tok0 + j) * 2);

        const float4* vb4 = (const float4*)(value_cache + base);
        const int dsub = lane >> 2;      // dim sub-index within each k group
        const int gsel = lane & 3;       // token-group lane id

        #pragma unroll
        for (int kk = 0; kk < 2; kk++) {
            float accv[Q_PER_KV][8];
            #pragma unroll
            for (int h = 0; h < Q_PER_KV; h++)
                #pragma unroll
                for (int j = 0; j < 8; j++) accv[h][j] = 0.f;

            #pragma unroll
            for (int j = 0; j < 8; j++) {
                const int k = kk * 8 + j;
                const float4 v = vb4[k * 32 + lane];
                #pragma unroll
                for (int h = 0; h < Q_PER_KV; h++)
                    accv[h][j] = v.x * ptok[h][0] + v.y * ptok[h][1]
                               + v.z * ptok[h][2] + v.w * ptok[h][3];
            }
            // combine the 4 token-group lanes (xor over bits 0,1), write to smem
            #pragma unroll
            for (int h = 0; h < Q_PER_KV; h++) {
                #pragma unroll
                for (int j = 0; j < 8; j++) {
                    float v = accv[h][j];
                    v += __shfl_xor_sync(0xffffffffu, v, 1);
                    v += __shfl_xor_sync(0xffffffffu, v, 2);
                    if (gsel == 0)
                        w_acc[warp][h][(kk * 8 + j) * 8 + dsub] = v;
                }
            }
        }
    } else if (lane == 0) {
        #pragma unroll
        for (int h = 0; h < Q_PER_KV; h++) { w_m[warp][h] = -1e30f; w_l[warp][h] = 0.f; }
    }
    __syncthreads();

    // ---- CTA merge of 8 warps -> split partial
    if (tid < Q_PER_KV) {
        const int h = tid;
        float mg = -1e30f;
        #pragma unroll
        for (int w = 0; w < NWARPS; w++) mg = fmaxf(mg, w_m[w][h]);
        float den = 0.f;
        #pragma unroll
        for (int w = 0; w < NWARPS; w++) den += w_l[w][h] * __expf(w_m[w][h] - mg);
        g_ml[seq][kvh][split][h][0] = mg;
        g_ml[seq][kvh][split][h][1] = den;
    }
    for (int o = tid; o < Q_PER_KV * HEAD_SIZE; o += 256) {
        const int h = o >> 7;
        const int d = o & 127;
        float mg = -1e30f;
        #pragma unroll
        for (int w = 0; w < NWARPS; w++) mg = fmaxf(mg, w_m[w][h]);
        float num = 0.f;
        #pragma unroll
        for (int w = 0; w < NWARPS; w++) num += w_acc[w][h][d] * __expf(w_m[w][h] - mg);
        g_acc[seq][kvh][split][h][d] = num;
    }
}

__global__ __launch_bounds__(256)
void paged_attn_merge(const int* __restrict__ context_lens,
                      float* __restrict__ out)
{
    const int warp = threadIdx.x >> 5;
    const int lane = threadIdx.x & 31;
    const int gid  = blockIdx.x * 8 + warp;     // one warp per (seq, head)
    const int seq  = gid >> 5;
    const int head = gid & 31;
    const int kvh  = head >> 2;
    const int h    = head & 3;

    const int ctx     = context_lens[seq];
    const int nblocks = (ctx + BLOCK_SIZE - 1) / BLOCK_SIZE;
    const int nsplits = (nblocks + BLOCKS_PER_SPLIT - 1) / BLOCKS_PER_SPLIT;

    float ms[SPLITS], ls[SPLITS];
    #pragma unroll
    for (int s = 0; s < SPLITS; s++) {
        if (s < nsplits) { ms[s] = g_ml[seq][kvh][s][h][0]; ls[s] = g_ml[seq][kvh][s][h][1]; }
        else             { ms[s] = -1e30f;                  ls[s] = 0.f; }
    }
    float gm = -1e30f;
    #pragma unroll
    for (int s = 0; s < SPLITS; s++) gm = fmaxf(gm, ms[s]);

    float4 num = make_float4(0.f, 0.f, 0.f, 0.f);
    float den = 0.f;
    #pragma unroll
    for (int s = 0; s < SPLITS; s++) {
        const float f = __expf(ms[s] - gm);
        den += ls[s] * f;
        if (s < nsplits) {
            const float4 a = *(const float4*)&g_acc[seq][kvh][s][h][lane * 4];
            num.x += a.x * f; num.y += a.y * f; num.z += a.z * f; num.w += a.w * f;
        }
    }
    const float inv = 1.f / den;
    float4 o = make_float4(num.x * inv, num.y * inv, num.z * inv, num.w * inv);
    *(float4*)(out + (size_t)(seq * NUM_HEADS + head) * HEAD_SIZE + lane * 4) = o;
}

extern "C" void kernel_launch(void* const* d_in, const int* in_sizes, int n_in,
                              void* d_out, int out_size)
{
    const float* query       = (const float*)d_in[0];
    const float* key_cache   = (const float*)d_in[1];
    const float* value_cache = (const float*)d_in[2];
    const int*   block_tables  = (const int*)d_in[3];
    const int*   context_lens  = (const int*)d_in[4];
    float* out = (float*)d_out;

    dim3 grid1(NUM_KV_HEADS, NUM_SEQS, SPLITS);
    paged_attn_partial<<<grid1, 256>>>(query, key_cache, value_cache,
                                       block_tables, context_lens);
    paged_attn_merge<<<NUM_SEQS * NUM_HEADS / 8, 256>>>(context_lens, out);
}

// round 4
// speedup vs baseline: 2.5789x; 1.0734x over previous
#include <cuda_runtime.h>
#include <float.h>

#define NUM_SEQS 64
#define NUM_HEADS 32
#define NUM_KV_HEADS 8
#define HEAD_SIZE 128
#define BLOCK_SIZE 16
#define MAX_BLOCKS_PER_SEQ 64
#define Q_PER_KV 4
#define ATTN_SCALE 0.08838834764831845f

#define NWARPS 8
#define SPLITS 4
#define BLOCKS_PER_SPLIT 16      // 8 warps x 2 blocks

__device__ float g_acc[NUM_SEQS][NUM_KV_HEADS][SPLITS][Q_PER_KV][HEAD_SIZE];
__device__ float g_ml [NUM_SEQS][NUM_KV_HEADS][SPLITS][Q_PER_KV][2];

__global__ __launch_bounds__(256, 2)
void paged_attn_partial(const float* __restrict__ query,
                        const float* __restrict__ key_cache,
                        const float* __restrict__ value_cache,
                        const int*   __restrict__ block_tables,
                        const int*   __restrict__ context_lens)
{
    const int kvh   = blockIdx.x;
    const int seq   = blockIdx.y;
    const int split = blockIdx.z;
    const int tid   = threadIdx.x;
    const int warp  = tid >> 5;
    const int lane  = tid & 31;

    const int ctx     = context_lens[seq];
    const int nblocks = (ctx + BLOCK_SIZE - 1) / BLOCK_SIZE;
    if (split * BLOCKS_PER_SPLIT >= nblocks) return;

    __shared__ float q_s[Q_PER_KV * HEAD_SIZE];
    __shared__ float w_m[NWARPS][Q_PER_KV];
    __shared__ float w_l[NWARPS][Q_PER_KV];
    __shared__ float w_acc[NWARPS][Q_PER_KV][HEAD_SIZE];

    for (int i = tid; i < Q_PER_KV * HEAD_SIZE; i += 256)
        q_s[i] = query[(size_t)(seq * NUM_HEADS + kvh * Q_PER_KV) * HEAD_SIZE + i] * ATTN_SCALE;
    for (int i = tid; i < NWARPS * Q_PER_KV * HEAD_SIZE; i += 256)
        ((float*)w_acc)[i] = 0.f;
    __syncthreads();

    const int blk0 = split * BLOCKS_PER_SPLIT + warp * 2;
    const int blk1 = blk0 + 1;
    const bool have0 = blk0 < nblocks;
    const bool have1 = blk1 < nblocks;

    if (have0) {
        const int pb0 = block_tables[seq * MAX_BLOCKS_PER_SEQ + blk0];
        const int pb1 = have1 ? block_tables[seq * MAX_BLOCKS_PER_SEQ + blk1] : pb0;
        const size_t base0 = ((size_t)pb0 * NUM_KV_HEADS + kvh) * 2048;
        const size_t base1 = ((size_t)pb1 * NUM_KV_HEADS + kvh) * 2048;

        // prefetch both V tiles to L2 while the K phase runs
        {
            const char* v0 = (const char*)(value_cache + base0);
            const char* v1 = (const char*)(value_cache + base1);
            asm volatile("prefetch.global.L2 [%0];" :: "l"(v0 + lane * 128));
            asm volatile("prefetch.global.L2 [%0];" :: "l"(v0 + 4096 + lane * 128));
            asm volatile("prefetch.global.L2 [%0];" :: "l"(v1 + lane * 128));
            asm volatile("prefetch.global.L2 [%0];" :: "l"(v1 + 4096 + lane * 128));
        }

        const int t_lane = lane >> 1;          // token 0..15
        const int dl0    = (lane & 1) * 4;     // 4-dim sub-slot within each 8-dim group

        // ---- K: fully coalesced. lane reads float4 at j*32+lane ->
        //      (token lane>>1, dims j*8 + dl0 .. +3)
        const float4* kb0 = (const float4*)(key_cache + base0);
        const float4* kb1 = (const float4*)(key_cache + base1);

        float s0[Q_PER_KV] = {0.f, 0.f, 0.f, 0.f};
        float s1[Q_PER_KV] = {0.f, 0.f, 0.f, 0.f};

        #pragma unroll
        for (int batch = 0; batch < 2; batch++) {
            float4 kr0[8], kr1[8];
            #pragma unroll
            for (int i = 0; i < 8; i++) {
                const int j = batch * 8 + i;
                kr0[i] = kb0[j * 32 + lane];
                kr1[i] = kb1[j * 32 + lane];
            }
            #pragma unroll
            for (int i = 0; i < 8; i++) {
                const int j = batch * 8 + i;
                #pragma unroll
                for (int h = 0; h < Q_PER_KV; h++) {
                    const float4 q4 = *(const float4*)(q_s + h * HEAD_SIZE + j * 8 + dl0);
                    s0[h] += q4.x * kr0[i].x + q4.y * kr0[i].y + q4.z * kr0[i].z + q4.w * kr0[i].w;
                    s1[h] += q4.x * kr1[i].x + q4.y * kr1[i].y + q4.z * kr1[i].z + q4.w * kr1[i].w;
                }
            }
        }
        // pair combine (lanes 2t / 2t+1 hold complementary dim halves)
        #pragma unroll
        for (int h = 0; h < Q_PER_KV; h++) {
            s0[h] += __shfl_xor_sync(0xffffffffu, s0[h], 1);
            s1[h] += __shfl_xor_sync(0xffffffffu, s1[h], 1);
        }

        const bool valid0 = (blk0 * BLOCK_SIZE + t_lane) < ctx;
        const bool valid1 = have1 && ((blk1 * BLOCK_SIZE + t_lane) < ctx);
        #pragma unroll
        for (int h = 0; h < Q_PER_KV; h++) {
            s0[h] = valid0 ? s0[h] : -1e30f;
            s1[h] = valid1 ? s1[h] : -1e30f;
        }

        // ---- joint softmax over the 32 tokens of both blocks
        float p0[Q_PER_KV], p1[Q_PER_KV];
        #pragma unroll
        for (int h = 0; h < Q_PER_KV; h++) {
            float bm = fmaxf(s0[h], s1[h]);
            #pragma unroll
            for (int off = 2; off < 32; off <<= 1)
                bm = fmaxf(bm, __shfl_xor_sync(0xffffffffu, bm, off));
            p0[h] = __expf(s0[h] - bm);
            p1[h] = __expf(s1[h] - bm);
            float ps = p0[h] + p1[h];
            #pragma unroll
            for (int off = 2; off < 32; off <<= 1)
                ps += __shfl_xor_sync(0xffffffffu, ps, off);
            if (lane == 0) { w_m[warp][h] = bm; w_l[warp][h] = ps; }
        }

        // ---- probs for this lane's 4 tokens (per block)
        float pt0[Q_PER_KV][4], pt1[Q_PER_KV][4];
        const int tok0 = (lane & 3) * 4;
        #pragma unroll
        for (int h = 0; h < Q_PER_KV; h++)
            #pragma unroll
            for (int j = 0; j < 4; j++) {
                pt0[h][j] = __shfl_sync(0xffffffffu, p0[h], (tok0 + j) * 2);
                pt1[h][j] = __shfl_sync(0xffffffffu, p1[h], (tok0 + j) * 2);
            }

        // ---- V: coalesced; lane = (dim 8k + lane/4, tokens tok0..tok0+3)
        const float4* vb0 = (const float4*)(value_cache + base0);
        const float4* vb1 = (const float4*)(value_cache + base1);
        const int dsub = lane >> 2;
        const int gsel = lane & 3;

        #pragma unroll
        for (int kk = 0; kk < 2; kk++) {
            float accv[Q_PER_KV][8];
            #pragma unroll
            for (int j = 0; j < 8; j++) {
                const int k = kk * 8 + j;
                const float4 v0 = vb0[k * 32 + lane];
                const float4 v1 = vb1[k * 32 + lane];
                #pragma unroll
                for (int h = 0; h < Q_PER_KV; h++)
                    accv[h][j] = v0.x * pt0[h][0] + v0.y * pt0[h][1]
                               + v0.z * pt0[h][2] + v0.w * pt0[h][3]
                               + v1.x * pt1[h][0] + v1.y * pt1[h][1]
                               + v1.z * pt1[h][2] + v1.w * pt1[h][3];
            }
            #pragma unroll
            for (int h = 0; h < Q_PER_KV; h++) {
                #pragma unroll
                for (int j = 0; j < 8; j++) {
                    float v = accv[h][j];
                    v += __shfl_xor_sync(0xffffffffu, v, 1);
                    v += __shfl_xor_sync(0xffffffffu, v, 2);
                    if (gsel == 0)
                        w_acc[warp][h][(kk * 8 + j) * 8 + dsub] = v;
                }
            }
        }
    } else if (lane == 0) {
        #pragma unroll
        for (int h = 0; h < Q_PER_KV; h++) { w_m[warp][h] = -1e30f; w_l[warp][h] = 0.f; }
    }
    __syncthreads();

    // ---- CTA merge of 8 warps -> split partial
    if (tid < Q_PER_KV) {
        const int h = tid;
        float mg = -1e30f;
        #pragma unroll
        for (int w = 0; w < NWARPS; w++) mg = fmaxf(mg, w_m[w][h]);
        float den = 0.f;
        #pragma unroll
        for (int w = 0; w < NWARPS; w++) den += w_l[w][h] * __expf(w_m[w][h] - mg);
        g_ml[seq][kvh][split][h][0] = mg;
        g_ml[seq][kvh][split][h][1] = den;
    }
    for (int o = tid; o < Q_PER_KV * HEAD_SIZE; o += 256) {
        const int h = o >> 7;
        const int d = o & 127;
        float mg = -1e30f;
        #pragma unroll
        for (int w = 0; w < NWARPS; w++) mg = fmaxf(mg, w_m[w][h]);
        float num = 0.f;
        #pragma unroll
        for (int w = 0; w < NWARPS; w++) num += w_acc[w][h][d] * __expf(w_m[w][h] - mg);
        g_acc[seq][kvh][split][h][d] = num;
    }
}

__global__ __launch_bounds__(256)
void paged_attn_merge(const int* __restrict__ context_lens,
                      float* __restrict__ out)
{
    const int warp = threadIdx.x >> 5;
    const int lane = threadIdx.x & 31;
    const int gid  = blockIdx.x * 8 + warp;     // one warp per (seq, head)
    const int seq  = gid >> 5;
    const int head = gid & 31;
    const int kvh  = head >> 2;
    const int h    = head & 3;

    const int ctx     = context_lens[seq];
    const int nblocks = (ctx + BLOCK_SIZE - 1) / BLOCK_SIZE;
    const int nsplits = (nblocks + BLOCKS_PER_SPLIT - 1) / BLOCKS_PER_SPLIT;

    float ms[SPLITS], ls[SPLITS];
    #pragma unroll
    for (int s = 0; s < SPLITS; s++) {
        if (s < nsplits) { ms[s] = g_ml[seq][kvh][s][h][0]; ls[s] = g_ml[seq][kvh][s][h][1]; }
        else             { ms[s] = -1e30f;                  ls[s] = 0.f; }
    }
    float gm = -1e30f;
    #pragma unroll
    for (int s = 0; s < SPLITS; s++) gm = fmaxf(gm, ms[s]);

    float4 num = make_float4(0.f, 0.f, 0.f, 0.f);
    float den = 0.f;
    #pragma unroll
    for (int s = 0; s < SPLITS; s++) {
        const float f = __expf(ms[s] - gm);
        den += ls[s] * f;
        if (s < nsplits) {
            const float4 a = *(const float4*)&g_acc[seq][kvh][s][h][lane * 4];
            num.x += a.x * f; num.y += a.y * f; num.z += a.z * f; num.w += a.w * f;
        }
    }
    const float inv = 1.f / den;
    float4 o = make_float4(num.x * inv, num.y * inv, num.z * inv, num.w * inv);
    *(float4*)(out + (size_t)(seq * NUM_HEADS + head) * HEAD_SIZE + lane * 4) = o;
}

extern "C" void kernel_launch(void* const* d_in, const int* in_sizes, int n_in,
                              void* d_out, int out_size)
{
    const float* query       = (const float*)d_in[0];
    const float* key_cache   = (const float*)d_in[1];
    const float* value_cache = (const float*)d_in[2];
    const int*   block_tables  = (const int*)d_in[3];
    const int*   context_lens  = (const int*)d_in[4];
    float* out = (float*)d_out;

    dim3 grid1(NUM_KV_HEADS, NUM_SEQS, SPLITS);
    paged_attn_partial<<<grid1, 256>>>(query, key_cache, value_cache,
                                       block_tables, context_lens);
    paged_attn_merge<<<NUM_SEQS * NUM_HEADS / 8, 256>>>(context_lens, out);
}